// round 7
// baseline (speedup 1.0000x reference)
#include <cuda_runtime.h>
#include <cuda_bf16.h>
#include <cstdint>

// CapsNet dynamic routing. u_hat never materialized; bf16 hi/lo 3-pass GEMMs
// on mma.sync (m16n8k16, fp32 accum).
//   inp: [256,1152,8] fp32, W: [1152,10,16,8] fp32, out v: [256,10,16] fp32
//
// All __device__ globals referenced only inside device code (host-passed
// __device__ symbols silently resolve to ATS host memory on GB300).

#define BATCH   256
#define INCH    1152
#define INU     8
#define OUTCH   10
#define OUTU    16
#define KDIM    (INCH*INU)     // 9216
#define NDIM    (OUTCH*OUTU)   // 160
#define NCHUNK  144            // 64-k chunks (8 capsules each)
#define SPLITS_S 36            // s-GEMM K splits (4 chunks = 256 K per CTA)

// ---------------- device globals ----------------
__device__ __nv_bfloat16 g_inp_hi[BATCH * KDIM];
__device__ __nv_bfloat16 g_inp_lo[BATCH * KDIM];
__device__ __nv_bfloat16 g_inpT_hi[KDIM * BATCH];
__device__ __nv_bfloat16 g_inpT_lo[KDIM * BATCH];
__device__ __nv_bfloat16 g_vT_hi[NDIM * BATCH];
__device__ __nv_bfloat16 g_vT_lo[NDIM * BATCH];
__device__ __nv_bfloat16 g_Bt_hi[NCHUNK * NDIM * 64];  // chunk-tiled Wc
__device__ __nv_bfloat16 g_Bt_lo[NCHUNK * NDIM * 64];
__device__ float g_part_s[SPLITS_S * BATCH * NDIM];    // 5.9 MB
__device__ float g_b[INCH * OUTCH];

__device__ __forceinline__ uint32_t smem_to_u32(const void* p) {
    uint32_t a;
    asm("{ .reg .u64 t; cvta.to.shared.u64 t, %1; cvt.u32.u64 %0, t; }"
        : "=r"(a) : "l"(p));
    return a;
}
__device__ __forceinline__ void split_bf16(float x, __nv_bfloat16& h, __nv_bfloat16& l) {
    h = __float2bfloat16(x);
    l = __float2bfloat16(x - __bfloat162float(h));
}
__device__ __forceinline__ void ldsm4(uint32_t& r0, uint32_t& r1, uint32_t& r2,
                                      uint32_t& r3, uint32_t addr) {
    asm volatile("ldmatrix.sync.aligned.m8n8.x4.shared.b16 {%0,%1,%2,%3}, [%4];"
                 : "=r"(r0), "=r"(r1), "=r"(r2), "=r"(r3) : "r"(addr));
}
__device__ __forceinline__ void mma16816(float* d, const uint32_t* a,
                                         const uint32_t* b) {
    asm volatile(
        "mma.sync.aligned.m16n8k16.row.col.f32.bf16.bf16.f32 "
        "{%0,%1,%2,%3}, {%4,%5,%6,%7}, {%8,%9}, {%0,%1,%2,%3};"
        : "+f"(d[0]), "+f"(d[1]), "+f"(d[2]), "+f"(d[3])
        : "r"(a[0]), "r"(a[1]), "r"(a[2]), "r"(a[3]), "r"(b[0]), "r"(b[1]));
}
__device__ __forceinline__ void cp16(uint32_t dst, const void* src) {
    asm volatile("cp.async.cg.shared.global [%0], [%1], 16;"
                 :: "r"(dst), "l"(src));
}
__device__ __forceinline__ void cp_commit() {
    asm volatile("cp.async.commit_group;");
}
template <int N>
__device__ __forceinline__ void cp_wait() {
    asm volatile("cp.async.wait_group %0;" :: "n"(N));
}

// ---------------------------------------------------------------------------
// One-time: inp fp32 -> bf16 hi/lo, plus transposed copies.
// ---------------------------------------------------------------------------
__global__ void conv_inp(const float* __restrict__ inp) {
    __shared__ __nv_bfloat16 sh_hi[32][33];
    __shared__ __nv_bfloat16 sh_lo[32][33];
    int ik0 = blockIdx.x * 32, b0 = blockIdx.y * 32;
    int tx = threadIdx.x, ty = threadIdx.y;
    #pragma unroll
    for (int j = 0; j < 4; j++) {
        int bl = ty + 8 * j;
        float x = inp[(size_t)(b0 + bl) * KDIM + ik0 + tx];
        __nv_bfloat16 h, l;
        split_bf16(x, h, l);
        g_inp_hi[(size_t)(b0 + bl) * KDIM + ik0 + tx] = h;
        g_inp_lo[(size_t)(b0 + bl) * KDIM + ik0 + tx] = l;
        sh_hi[tx][bl] = h;
        sh_lo[tx][bl] = l;
    }
    __syncthreads();
    #pragma unroll
    for (int j = 0; j < 4; j++) {
        int ikl = ty + 8 * j;
        g_inpT_hi[(size_t)(ik0 + ikl) * BATCH + b0 + tx] = sh_hi[ikl][tx];
        g_inpT_lo[(size_t)(ik0 + ikl) * BATCH + b0 + tx] = sh_lo[ikl][tx];
    }
}

// ---------------------------------------------------------------------------
// Wc build, chunk-tiled: g_Bt[chunk][ou][64] = c[i,o]*W[i,o,u,k] (bf16 hi/lo).
// One CTA per chunk of 8 capsules. Fully coalesced read and write.
// ---------------------------------------------------------------------------
__global__ void wc_tiled(const float* __restrict__ W, int t) {
    __shared__ float c_s[8][10];
    int chunk = blockIdx.x, i0 = chunk * 8;
    int tid = threadIdx.x;
    if (tid < 8) {
        int i = i0 + tid;
        if (t == 0) {
            #pragma unroll
            for (int o = 0; o < OUTCH; o++) c_s[tid][o] = 0.1f;
        } else {
            float bv[OUTCH], m = -1e30f;
            #pragma unroll
            for (int o = 0; o < OUTCH; o++) {
                bv[o] = g_b[i * OUTCH + o];
                m = fmaxf(m, bv[o]);
            }
            float sum = 0.f;
            #pragma unroll
            for (int o = 0; o < OUTCH; o++) { bv[o] = expf(bv[o] - m); sum += bv[o]; }
            float inv = 1.0f / sum;
            #pragma unroll
            for (int o = 0; o < OUTCH; o++) c_s[tid][o] = bv[o] * inv;
        }
    }
    __syncthreads();
    const float4* W4 = (const float4*)(W + (size_t)i0 * 1280);
    __nv_bfloat16* bh = g_Bt_hi + (size_t)chunk * (NDIM * 64);
    __nv_bfloat16* bl = g_Bt_lo + (size_t)chunk * (NDIM * 64);
    #pragma unroll
    for (int r = 0; r < 10; r++) {
        int q = tid + (r << 8);              // 0..2559 float4s (8 caps x 320)
        int i_off = q / 320;
        int rem = q - i_off * 320;
        int o = rem >> 5;
        int rem2 = rem & 31;
        int u = rem2 >> 1, kh = rem2 & 1;
        float4 f = W4[q];
        float cv = c_s[i_off][o];
        __nv_bfloat16 h0,l0,h1,l1,h2,l2,h3,l3;
        split_bf16(f.x * cv, h0, l0);
        split_bf16(f.y * cv, h1, l1);
        split_bf16(f.z * cv, h2, l2);
        split_bf16(f.w * cv, h3, l3);
        uint2 ph, pl;
        ph.x = (uint32_t)__bfloat16_as_ushort(h0) | ((uint32_t)__bfloat16_as_ushort(h1) << 16);
        ph.y = (uint32_t)__bfloat16_as_ushort(h2) | ((uint32_t)__bfloat16_as_ushort(h3) << 16);
        pl.x = (uint32_t)__bfloat16_as_ushort(l0) | ((uint32_t)__bfloat16_as_ushort(l1) << 16);
        pl.y = (uint32_t)__bfloat16_as_ushort(l2) | ((uint32_t)__bfloat16_as_ushort(l3) << 16);
        int off = (o * 16 + u) * 64 + i_off * 8 + kh * 4;
        *(uint2*)(bh + off) = ph;
        *(uint2*)(bl + off) = pl;
    }
}

// ---------------------------------------------------------------------------
// Shared GEMM geometry: 256 thr, 8 warps (4M x 2N), warp tile 16x80,
// CTA tile 64(M) x 160(N), 12 pipeline stages (3 hi/lo passes x 4 K-chunks),
// cp.async double-buffered.
// ---------------------------------------------------------------------------
#define PITCH 72   // bf16 smem row pitch (144 B, ldmatrix conflict-free)
#define SG_AS 0
#define SG_BS (64*PITCH*2)                  // 9216
#define SG_STAGE (SG_BS + 160*PITCH*2)      // 32256 bytes per stage
#define SG_TOT (2*SG_STAGE)                 // 64512

// ---------------------------------------------------------------------------
// s-GEMM: grid (4 Mtiles, 36 Ksplits). A = g_inp (row stride KDIM),
// B = g_Bt chunk-tiled. Partial tile -> g_part_s[ksplit].
// ---------------------------------------------------------------------------
__global__ void __launch_bounds__(256, 2)
gemm_s(int t_unused) {
    extern __shared__ char sm[];
    uint32_t sb = smem_to_u32(sm);
    int tid = threadIdx.x, lane = tid & 31, wid = tid >> 5;
    int warp_m = wid & 3, warp_n = wid >> 2;
    int m0 = blockIdx.x * 64;

    auto issue = [&](int g) {
        int p = g >> 2, c = g & 3;
        int chunk = blockIdx.y * 4 + c;
        const __nv_bfloat16* Asrc = (p == 2) ? g_inp_lo : g_inp_hi;
        const __nv_bfloat16* Bsrc = (p == 1) ? g_Bt_lo : g_Bt_hi;
        uint32_t base = sb + (g & 1) * SG_STAGE;
        #pragma unroll
        for (int r = 0; r < 2; r++) {
            int e = tid + (r << 8);
            int row = e >> 3, j = e & 7;
            cp16(base + SG_AS + (uint32_t)(row * PITCH + j * 8) * 2,
                 Asrc + (size_t)(m0 + row) * KDIM + chunk * 64 + j * 8);
        }
        #pragma unroll
        for (int r = 0; r < 5; r++) {
            int e = tid + (r << 8);
            int row = e >> 3, j = e & 7;
            cp16(base + SG_BS + (uint32_t)(row * PITCH + j * 8) * 2,
                 Bsrc + (size_t)chunk * (NDIM * 64) + e * 8);
        }
        cp_commit();
    };

    float acc[10][4];
    #pragma unroll
    for (int nt = 0; nt < 10; nt++)
        #pragma unroll
        for (int r = 0; r < 4; r++) acc[nt][r] = 0.f;

    int a_row_l = ((lane >> 3) & 1) * 8 + (lane & 7);
    int a_k_l   = (lane >> 4) * 8;
    int b_dn_l  = ((lane >> 4) & 1) * 8 + (lane & 7);
    int b_dk_l  = ((lane >> 3) & 1) * 8;

    issue(0);
    for (int g = 0; g < 12; g++) {
        if (g + 1 < 12) {
            issue(g + 1);
            cp_wait<1>();
        } else {
            cp_wait<0>();
        }
        __syncthreads();
        uint32_t base = sb + (g & 1) * SG_STAGE;
        #pragma unroll
        for (int ks = 0; ks < 4; ks++) {
            uint32_t af[4], bf[10][2];
            int row = warp_m * 16 + a_row_l;
            ldsm4(af[0], af[1], af[2], af[3],
                  base + SG_AS + (uint32_t)(row * PITCH + ks * 16 + a_k_l) * 2);
            #pragma unroll
            for (int p = 0; p < 5; p++) {
                int brow = warp_n * 80 + p * 16 + b_dn_l;
                ldsm4(bf[2*p][0], bf[2*p][1], bf[2*p+1][0], bf[2*p+1][1],
                      base + SG_BS + (uint32_t)(brow * PITCH + ks * 16 + b_dk_l) * 2);
            }
            #pragma unroll
            for (int nt = 0; nt < 10; nt++)
                mma16816(acc[nt], af, bf[nt]);
        }
        __syncthreads();
    }

    float* out = g_part_s + (size_t)blockIdx.y * (BATCH * NDIM);
    int r_l = lane >> 2, c_l = (lane & 3) * 2;
    int row = m0 + warp_m * 16 + r_l;
    #pragma unroll
    for (int nt = 0; nt < 10; nt++) {
        int col = warp_n * 80 + nt * 8 + c_l;
        *(float2*)(out + (size_t)row * NDIM + col) = make_float2(acc[nt][0], acc[nt][1]);
        *(float2*)(out + (size_t)(row + 8) * NDIM + col) = make_float2(acc[nt][2], acc[nt][3]);
    }
}

// ---------------------------------------------------------------------------
// Split-K reduce + squash, 2-level: 640 blocks, 256 thr = 64 elems x 4 groups
// of 9 splits; smem combine, then 16-wide shuffle norm.
// ---------------------------------------------------------------------------
__global__ void squash_k(float* __restrict__ out, int t) {
    __shared__ float red[4][64];
    int e_l = threadIdx.x & 63;
    int grp = threadIdx.x >> 6;        // 0..3
    int idx = blockIdx.x * 64 + e_l;   // b*160 + o*16 + u

    float a0 = 0.f, a1 = 0.f, a2 = 0.f;
    #pragma unroll
    for (int j = 0; j < 9; j += 3) {
        a0 += g_part_s[(size_t)(grp * 9 + j + 0) * (BATCH * NDIM) + idx];
        a1 += g_part_s[(size_t)(grp * 9 + j + 1) * (BATCH * NDIM) + idx];
        a2 += g_part_s[(size_t)(grp * 9 + j + 2) * (BATCH * NDIM) + idx];
    }
    red[grp][e_l] = (a0 + a1) + a2;
    __syncthreads();
    if (threadIdx.x < 64) {
        float s = (red[0][e_l] + red[1][e_l]) + (red[2][e_l] + red[3][e_l]);
        float sq = s * s;
        sq += __shfl_xor_sync(0xffffffffu, sq, 8);
        sq += __shfl_xor_sync(0xffffffffu, sq, 4);
        sq += __shfl_xor_sync(0xffffffffu, sq, 2);
        sq += __shfl_xor_sync(0xffffffffu, sq, 1);
        float scale = sq / ((1.0f + sq) * sqrtf(sq + 1e-9f));
        float v = s * scale;
        if (t == 2) {
            out[idx] = v;
        } else {
            int b = idx / NDIM;
            int ou = idx - b * NDIM;
            __nv_bfloat16 h, l;
            split_bf16(v, h, l);
            g_vT_hi[(size_t)ou * BATCH + b] = h;
            g_vT_lo[(size_t)ou * BATCH + b] = l;
        }
    }
}

// ---------------------------------------------------------------------------
// M-GEMM (M[ik,ou] = inpT @ vT^T) with fused b-update.
// grid 144 (64 ik rows = 8 capsules per CTA), K=256 over 3 passes x 4 chunks.
// ---------------------------------------------------------------------------
__global__ void __launch_bounds__(256, 2)
gemm_m(const float* __restrict__ W, int t) {
    extern __shared__ char sm[];
    uint32_t sb = smem_to_u32(sm);
    int tid = threadIdx.x, lane = tid & 31, wid = tid >> 5;
    int warp_m = wid & 3, warp_n = wid >> 2;
    int m0 = blockIdx.x * 64;

    auto issue = [&](int g) {
        int p = g >> 2, c = g & 3;
        const __nv_bfloat16* Asrc = (p == 2) ? g_inpT_lo : g_inpT_hi;
        const __nv_bfloat16* Bsrc = (p == 1) ? g_vT_lo : g_vT_hi;
        int kb = c << 6;
        uint32_t base = sb + (g & 1) * SG_STAGE;
        #pragma unroll
        for (int r = 0; r < 2; r++) {
            int e = tid + (r << 8);
            int row = e >> 3, j = e & 7;
            cp16(base + SG_AS + (uint32_t)(row * PITCH + j * 8) * 2,
                 Asrc + (size_t)(m0 + row) * BATCH + kb + j * 8);
        }
        #pragma unroll
        for (int r = 0; r < 5; r++) {
            int e = tid + (r << 8);
            int row = e >> 3, j = e & 7;
            cp16(base + SG_BS + (uint32_t)(row * PITCH + j * 8) * 2,
                 Bsrc + (size_t)row * BATCH + kb + j * 8);
        }
        cp_commit();
    };

    float acc[10][4];
    #pragma unroll
    for (int nt = 0; nt < 10; nt++)
        #pragma unroll
        for (int r = 0; r < 4; r++) acc[nt][r] = 0.f;

    int a_row_l = ((lane >> 3) & 1) * 8 + (lane & 7);
    int a_k_l   = (lane >> 4) * 8;
    int b_dn_l  = ((lane >> 4) & 1) * 8 + (lane & 7);
    int b_dk_l  = ((lane >> 3) & 1) * 8;

    issue(0);
    for (int g = 0; g < 12; g++) {
        if (g + 1 < 12) {
            issue(g + 1);
            cp_wait<1>();
        } else {
            cp_wait<0>();
        }
        __syncthreads();
        uint32_t base = sb + (g & 1) * SG_STAGE;
        #pragma unroll
        for (int ks = 0; ks < 4; ks++) {
            uint32_t af[4], bf[10][2];
            int row = warp_m * 16 + a_row_l;
            ldsm4(af[0], af[1], af[2], af[3],
                  base + SG_AS + (uint32_t)(row * PITCH + ks * 16 + a_k_l) * 2);
            #pragma unroll
            for (int p = 0; p < 5; p++) {
                int brow = warp_n * 80 + p * 16 + b_dn_l;
                ldsm4(bf[2*p][0], bf[2*p][1], bf[2*p+1][0], bf[2*p+1][1],
                      base + SG_BS + (uint32_t)(brow * PITCH + ks * 16 + b_dk_l) * 2);
            }
            #pragma unroll
            for (int nt = 0; nt < 10; nt++)
                mma16816(acc[nt], af, bf[nt]);
        }
        __syncthreads();
    }

    // Stage M tile [64][160] fp32 in smem (reuses pipeline buffers).
    float* M_s = (float*)sm;
    int r_l = lane >> 2, c_l = (lane & 3) * 2;
    int row = warp_m * 16 + r_l;
    #pragma unroll
    for (int nt = 0; nt < 10; nt++) {
        int col = warp_n * 80 + nt * 8 + c_l;
        *(float2*)(M_s + row * NDIM + col) = make_float2(acc[nt][0], acc[nt][1]);
        *(float2*)(M_s + (row + 8) * NDIM + col) = make_float2(acc[nt][2], acc[nt][3]);
    }
    __syncthreads();

    // Fused b-update: delta[i,o] = (1/B) sum_{k,u} W[i,o,u,k]*M[i8+k][o16+u]
    #pragma unroll
    for (int ee = 0; ee < 10; ee++) {
        int e = wid * 10 + ee;
        int i_rel = e / 10, o = e - i_rel * 10;
        int i = blockIdx.x * 8 + i_rel;
        float sum = 0.f;
        #pragma unroll
        for (int j = 0; j < 4; j++) {
            int f = lane + (j << 5);           // 0..127
            int k = f >> 4, u = f & 15;
            sum = fmaf(W[(size_t)i * 1280 + (o << 7) + (u << 3) + k],
                       M_s[(i_rel * 8 + k) * NDIM + o * 16 + u], sum);
        }
        #pragma unroll
        for (int off = 16; off; off >>= 1)
            sum += __shfl_xor_sync(0xffffffffu, sum, off);
        if (lane == 0) {
            float d = sum * (1.0f / (float)BATCH);
            int gw = i * OUTCH + o;
            g_b[gw] = (t == 0) ? d : (g_b[gw] + d);
        }
    }
}

// ---------------------------------------------------------------------------
extern "C" void kernel_launch(void* const* d_in, const int* in_sizes, int n_in,
                              void* d_out, int out_size) {
    const float* inp = (const float*)d_in[0];  // [256,1152,8]
    const float* W   = (const float*)d_in[1];  // [1152,10,16,8]
    float* out = (float*)d_out;                // [256,10,16]

    cudaFuncSetAttribute(gemm_s, cudaFuncAttributeMaxDynamicSharedMemorySize, SG_TOT);
    cudaFuncSetAttribute(gemm_m, cudaFuncAttributeMaxDynamicSharedMemorySize, SG_TOT);

    conv_inp<<<dim3(KDIM / 32, BATCH / 32), dim3(32, 8)>>>(inp);

    for (int t = 0; t < 3; t++) {
        wc_tiled<<<NCHUNK, 256>>>(W, t);
        gemm_s<<<dim3(4, SPLITS_S), 256, SG_TOT>>>(0);
        squash_k<<<BATCH * NDIM / 64, 256>>>(out, t);
        if (t < 2)
            gemm_m<<<KDIM / 64, 256, SG_TOT>>>(W, t);
    }
}

// round 8
// speedup vs baseline: 1.1687x; 1.1687x over previous
#include <cuda_runtime.h>
#include <cuda_bf16.h>
#include <cstdint>

// CapsNet dynamic routing. u_hat never materialized; bf16 hi/lo 3-pass GEMMs
// on mma.sync (m16n8k16, fp32 accum).
//   inp: [256,1152,8] fp32, W: [1152,10,16,8] fp32, out v: [256,10,16] fp32
//
// All __device__ globals referenced only inside device code (host-passed
// __device__ symbols silently resolve to ATS host memory on GB300).

#define BATCH   256
#define INCH    1152
#define INU     8
#define OUTCH   10
#define OUTU    16
#define KDIM    (INCH*INU)     // 9216
#define NDIM    (OUTCH*OUTU)   // 160
#define NCHUNK  144            // 64-k chunks (8 capsules each)
#define SPLITS_S 36            // s-GEMM K splits (4 chunks = 256 K per CTA)

// ---------------- device globals ----------------
__device__ __nv_bfloat16 g_inp_hi[BATCH * KDIM];
__device__ __nv_bfloat16 g_inp_lo[BATCH * KDIM];
__device__ __nv_bfloat16 g_inpT_hi[KDIM * BATCH];
__device__ __nv_bfloat16 g_inpT_lo[KDIM * BATCH];
__device__ __nv_bfloat16 g_vT_hi[NDIM * BATCH];
__device__ __nv_bfloat16 g_vT_lo[NDIM * BATCH];
__device__ __nv_bfloat16 g_Bt_hi[NCHUNK * NDIM * 64];  // chunk-tiled Wc
__device__ __nv_bfloat16 g_Bt_lo[NCHUNK * NDIM * 64];
__device__ float g_part_s[SPLITS_S * BATCH * NDIM];    // 5.9 MB
__device__ float g_b[INCH * OUTCH];

__device__ __forceinline__ uint32_t smem_to_u32(const void* p) {
    uint32_t a;
    asm("{ .reg .u64 t; cvta.to.shared.u64 t, %1; cvt.u32.u64 %0, t; }"
        : "=r"(a) : "l"(p));
    return a;
}
__device__ __forceinline__ void split_bf16(float x, __nv_bfloat16& h, __nv_bfloat16& l) {
    h = __float2bfloat16(x);
    l = __float2bfloat16(x - __bfloat162float(h));
}
__device__ __forceinline__ void ldsm4(uint32_t& r0, uint32_t& r1, uint32_t& r2,
                                      uint32_t& r3, uint32_t addr) {
    asm volatile("ldmatrix.sync.aligned.m8n8.x4.shared.b16 {%0,%1,%2,%3}, [%4];"
                 : "=r"(r0), "=r"(r1), "=r"(r2), "=r"(r3) : "r"(addr));
}
__device__ __forceinline__ void mma16816(float* d, const uint32_t* a,
                                         const uint32_t* b) {
    asm volatile(
        "mma.sync.aligned.m16n8k16.row.col.f32.bf16.bf16.f32 "
        "{%0,%1,%2,%3}, {%4,%5,%6,%7}, {%8,%9}, {%0,%1,%2,%3};"
        : "+f"(d[0]), "+f"(d[1]), "+f"(d[2]), "+f"(d[3])
        : "r"(a[0]), "r"(a[1]), "r"(a[2]), "r"(a[3]), "r"(b[0]), "r"(b[1]));
}
__device__ __forceinline__ void cp16(uint32_t dst, const void* src) {
    asm volatile("cp.async.cg.shared.global [%0], [%1], 16;"
                 :: "r"(dst), "l"(src));
}
__device__ __forceinline__ void cp_commit() {
    asm volatile("cp.async.commit_group;");
}
template <int N>
__device__ __forceinline__ void cp_wait() {
    asm volatile("cp.async.wait_group %0;" :: "n"(N));
}

// ---------------------------------------------------------------------------
// One-time: inp fp32 -> bf16 hi/lo, plus transposed copies.
// ---------------------------------------------------------------------------
__global__ void conv_inp(const float* __restrict__ inp) {
    __shared__ __nv_bfloat16 sh_hi[32][33];
    __shared__ __nv_bfloat16 sh_lo[32][33];
    int ik0 = blockIdx.x * 32, b0 = blockIdx.y * 32;
    int tx = threadIdx.x, ty = threadIdx.y;
    #pragma unroll
    for (int j = 0; j < 4; j++) {
        int bl = ty + 8 * j;
        float x = inp[(size_t)(b0 + bl) * KDIM + ik0 + tx];
        __nv_bfloat16 h, l;
        split_bf16(x, h, l);
        g_inp_hi[(size_t)(b0 + bl) * KDIM + ik0 + tx] = h;
        g_inp_lo[(size_t)(b0 + bl) * KDIM + ik0 + tx] = l;
        sh_hi[tx][bl] = h;
        sh_lo[tx][bl] = l;
    }
    __syncthreads();
    #pragma unroll
    for (int j = 0; j < 4; j++) {
        int ikl = ty + 8 * j;
        g_inpT_hi[(size_t)(ik0 + ikl) * BATCH + b0 + tx] = sh_hi[ikl][tx];
        g_inpT_lo[(size_t)(ik0 + ikl) * BATCH + b0 + tx] = sh_lo[ikl][tx];
    }
}

// ---------------------------------------------------------------------------
// Wc build, chunk-tiled: g_Bt[chunk][ou][64] = c[i,o]*W[i,o,u,k] (bf16 hi/lo).
// ---------------------------------------------------------------------------
__global__ void wc_tiled(const float* __restrict__ W, int t) {
    __shared__ float c_s[8][10];
    int chunk = blockIdx.x, i0 = chunk * 8;
    int tid = threadIdx.x;
    if (tid < 8) {
        int i = i0 + tid;
        if (t == 0) {
            #pragma unroll
            for (int o = 0; o < OUTCH; o++) c_s[tid][o] = 0.1f;
        } else {
            float bv[OUTCH], m = -1e30f;
            #pragma unroll
            for (int o = 0; o < OUTCH; o++) {
                bv[o] = g_b[i * OUTCH + o];
                m = fmaxf(m, bv[o]);
            }
            float sum = 0.f;
            #pragma unroll
            for (int o = 0; o < OUTCH; o++) { bv[o] = expf(bv[o] - m); sum += bv[o]; }
            float inv = 1.0f / sum;
            #pragma unroll
            for (int o = 0; o < OUTCH; o++) c_s[tid][o] = bv[o] * inv;
        }
    }
    __syncthreads();
    const float4* W4 = (const float4*)(W + (size_t)i0 * 1280);
    __nv_bfloat16* bh = g_Bt_hi + (size_t)chunk * (NDIM * 64);
    __nv_bfloat16* bl = g_Bt_lo + (size_t)chunk * (NDIM * 64);
    #pragma unroll
    for (int r = 0; r < 10; r++) {
        int q = tid + (r << 8);              // 0..2559 float4s (8 caps x 320)
        int i_off = q / 320;
        int rem = q - i_off * 320;
        int o = rem >> 5;
        int rem2 = rem & 31;
        int u = rem2 >> 1, kh = rem2 & 1;
        float4 f = W4[q];
        float cv = c_s[i_off][o];
        __nv_bfloat16 h0,l0,h1,l1,h2,l2,h3,l3;
        split_bf16(f.x * cv, h0, l0);
        split_bf16(f.y * cv, h1, l1);
        split_bf16(f.z * cv, h2, l2);
        split_bf16(f.w * cv, h3, l3);
        uint2 ph, pl;
        ph.x = (uint32_t)__bfloat16_as_ushort(h0) | ((uint32_t)__bfloat16_as_ushort(h1) << 16);
        ph.y = (uint32_t)__bfloat16_as_ushort(h2) | ((uint32_t)__bfloat16_as_ushort(h3) << 16);
        pl.x = (uint32_t)__bfloat16_as_ushort(l0) | ((uint32_t)__bfloat16_as_ushort(l1) << 16);
        pl.y = (uint32_t)__bfloat16_as_ushort(l2) | ((uint32_t)__bfloat16_as_ushort(l3) << 16);
        int off = (o * 16 + u) * 64 + i_off * 8 + kh * 4;
        *(uint2*)(bh + off) = ph;
        *(uint2*)(bl + off) = pl;
    }
}

// ---------------------------------------------------------------------------
// s-GEMM: grid (4 Mtiles, 36 Ksplits) = 144 CTAs, 256 thr, 8 warps (4M x 2N),
// CTA tile 64 x 160 x 256. ENTIRE working set (Ah,Al,Bh,Bl = 224 KB) staged
// via one-shot cp.async in 12 commit groups; 3 waits total (one per pass).
// Swizzled smem (col16 ^= row&7), 128B rows, zero padding.
// ---------------------------------------------------------------------------
#define SG2_AH 0            // 4 chunks x 64 rows x 128 B = 32768
#define SG2_AL 32768
#define SG2_BH 65536        // 4 chunks x 160 rows x 128 B = 81920
#define SG2_BL 147456
#define SG2_TOT 229376      // 224 KB

__device__ __forceinline__ uint32_t swz(uint32_t base, int row, int col16) {
    return base + (uint32_t)row * 128 + (uint32_t)((col16 ^ (row & 7)) << 4);
}

__global__ void __launch_bounds__(256, 1)
gemm_s(int t_unused) {
    extern __shared__ char sm[];
    uint32_t sb = smem_to_u32(sm);
    int tid = threadIdx.x, lane = tid & 31, wid = tid >> 5;
    int warp_m = wid & 3, warp_n = wid >> 2;
    int m0 = blockIdx.x * 64;
    int chunk0 = blockIdx.y * 4;

    // ---- issue all loads: groups 0..3 = (Ah+Bh)_c, 4..7 = Bl_c, 8..11 = Al_c
    #pragma unroll
    for (int c = 0; c < 4; c++) {
        int kb = (chunk0 + c) * 64;
        #pragma unroll
        for (int r = 0; r < 2; r++) {
            int e = tid + (r << 8);
            int row = e >> 3, j = e & 7;
            cp16(sb + swz(SG2_AH + c * 8192, row, j),
                 g_inp_hi + (size_t)(m0 + row) * KDIM + kb + j * 8);
        }
        #pragma unroll
        for (int r = 0; r < 5; r++) {
            int e = tid + (r << 8);
            int row = e >> 3, j = e & 7;
            cp16(sb + swz(SG2_BH + c * 20480, row, j),
                 g_Bt_hi + (size_t)(chunk0 + c) * (NDIM * 64) + e * 8);
        }
        cp_commit();
    }
    #pragma unroll
    for (int c = 0; c < 4; c++) {
        #pragma unroll
        for (int r = 0; r < 5; r++) {
            int e = tid + (r << 8);
            int row = e >> 3, j = e & 7;
            cp16(sb + swz(SG2_BL + c * 20480, row, j),
                 g_Bt_lo + (size_t)(chunk0 + c) * (NDIM * 64) + e * 8);
        }
        cp_commit();
    }
    #pragma unroll
    for (int c = 0; c < 4; c++) {
        int kb = (chunk0 + c) * 64;
        #pragma unroll
        for (int r = 0; r < 2; r++) {
            int e = tid + (r << 8);
            int row = e >> 3, j = e & 7;
            cp16(sb + swz(SG2_AL + c * 8192, row, j),
                 g_inp_lo + (size_t)(m0 + row) * KDIM + kb + j * 8);
        }
        cp_commit();
    }

    float acc[10][4];
    #pragma unroll
    for (int nt = 0; nt < 10; nt++)
        #pragma unroll
        for (int r = 0; r < 4; r++) acc[nt][r] = 0.f;

    int a_row_l = ((lane >> 3) & 1) * 8 + (lane & 7);
    int a_c16_l = lane >> 4;                  // 0/1
    int b_dn_l  = ((lane >> 4) & 1) * 8 + (lane & 7);
    int b_c16_l = (lane >> 3) & 1;            // 0/1

    auto do_chunk = [&](uint32_t aBase, uint32_t bBase) {
        #pragma unroll
        for (int ks = 0; ks < 4; ks++) {
            uint32_t af[4], bf[10][2];
            int arow = warp_m * 16 + a_row_l;
            ldsm4(af[0], af[1], af[2], af[3],
                  sb + swz(aBase, arow, (ks << 1) | a_c16_l));
            #pragma unroll
            for (int p = 0; p < 5; p++) {
                int brow = warp_n * 80 + p * 16 + b_dn_l;
                ldsm4(bf[2*p][0], bf[2*p][1], bf[2*p+1][0], bf[2*p+1][1],
                      sb + swz(bBase, brow, (ks << 1) | b_c16_l));
            }
            #pragma unroll
            for (int nt = 0; nt < 10; nt++)
                mma16816(acc[nt], af, bf[nt]);
        }
    };

    cp_wait<8>();       // groups 0..3 (Ah+Bh) complete
    __syncthreads();
    #pragma unroll
    for (int c = 0; c < 4; c++)
        do_chunk(SG2_AH + c * 8192, SG2_BH + c * 20480);
    cp_wait<4>();       // groups 4..7 (Bl) complete
    __syncthreads();
    #pragma unroll
    for (int c = 0; c < 4; c++)
        do_chunk(SG2_AH + c * 8192, SG2_BL + c * 20480);
    cp_wait<0>();       // groups 8..11 (Al) complete
    __syncthreads();
    #pragma unroll
    for (int c = 0; c < 4; c++)
        do_chunk(SG2_AL + c * 8192, SG2_BH + c * 20480);

    float* out = g_part_s + (size_t)blockIdx.y * (BATCH * NDIM);
    int r_l = lane >> 2, c_l = (lane & 3) * 2;
    int row = m0 + warp_m * 16 + r_l;
    #pragma unroll
    for (int nt = 0; nt < 10; nt++) {
        int col = warp_n * 80 + nt * 8 + c_l;
        *(float2*)(out + (size_t)row * NDIM + col) = make_float2(acc[nt][0], acc[nt][1]);
        *(float2*)(out + (size_t)(row + 8) * NDIM + col) = make_float2(acc[nt][2], acc[nt][3]);
    }
}

// ---------------------------------------------------------------------------
// Split-K reduce + squash, 2-level: 640 blocks, 256 thr = 64 elems x 4 groups
// of 9 splits; smem combine, then 16-wide shuffle norm.
// ---------------------------------------------------------------------------
__global__ void squash_k(float* __restrict__ out, int t) {
    __shared__ float red[4][64];
    int e_l = threadIdx.x & 63;
    int grp = threadIdx.x >> 6;        // 0..3
    int idx = blockIdx.x * 64 + e_l;   // b*160 + o*16 + u

    float a0 = 0.f, a1 = 0.f, a2 = 0.f;
    #pragma unroll
    for (int j = 0; j < 9; j += 3) {
        a0 += g_part_s[(size_t)(grp * 9 + j + 0) * (BATCH * NDIM) + idx];
        a1 += g_part_s[(size_t)(grp * 9 + j + 1) * (BATCH * NDIM) + idx];
        a2 += g_part_s[(size_t)(grp * 9 + j + 2) * (BATCH * NDIM) + idx];
    }
    red[grp][e_l] = (a0 + a1) + a2;
    __syncthreads();
    if (threadIdx.x < 64) {
        float s = (red[0][e_l] + red[1][e_l]) + (red[2][e_l] + red[3][e_l]);
        float sq = s * s;
        sq += __shfl_xor_sync(0xffffffffu, sq, 8);
        sq += __shfl_xor_sync(0xffffffffu, sq, 4);
        sq += __shfl_xor_sync(0xffffffffu, sq, 2);
        sq += __shfl_xor_sync(0xffffffffu, sq, 1);
        float scale = sq / ((1.0f + sq) * sqrtf(sq + 1e-9f));
        float v = s * scale;
        if (t == 2) {
            out[idx] = v;
        } else {
            int b = idx / NDIM;
            int ou = idx - b * NDIM;
            __nv_bfloat16 h, l;
            split_bf16(v, h, l);
            g_vT_hi[(size_t)ou * BATCH + b] = h;
            g_vT_lo[(size_t)ou * BATCH + b] = l;
        }
    }
}

// ---------------------------------------------------------------------------
// M-GEMM (M[ik,ou] = inpT @ vT^T) with fused b-update.
// grid 144 (64 ik rows = 8 capsules per CTA), K=256 over 3 passes x 4 chunks,
// cp.async 2-stage pipeline (PITCH=72 padded layout).
// ---------------------------------------------------------------------------
#define PITCH 72
#define SG_AS 0
#define SG_BS (64*PITCH*2)                  // 9216
#define SG_STAGE (SG_BS + 160*PITCH*2)      // 32256 bytes per stage
#define SG_TOT (2*SG_STAGE)                 // 64512

__global__ void __launch_bounds__(256, 1)
gemm_m(const float* __restrict__ W, int t) {
    extern __shared__ char sm[];
    uint32_t sb = smem_to_u32(sm);
    int tid = threadIdx.x, lane = tid & 31, wid = tid >> 5;
    int warp_m = wid & 3, warp_n = wid >> 2;
    int m0 = blockIdx.x * 64;

    auto issue = [&](int g) {
        int p = g >> 2, c = g & 3;
        const __nv_bfloat16* Asrc = (p == 2) ? g_inpT_lo : g_inpT_hi;
        const __nv_bfloat16* Bsrc = (p == 1) ? g_vT_lo : g_vT_hi;
        int kb = c << 6;
        uint32_t base = sb + (g & 1) * SG_STAGE;
        #pragma unroll
        for (int r = 0; r < 2; r++) {
            int e = tid + (r << 8);
            int row = e >> 3, j = e & 7;
            cp16(base + SG_AS + (uint32_t)(row * PITCH + j * 8) * 2,
                 Asrc + (size_t)(m0 + row) * BATCH + kb + j * 8);
        }
        #pragma unroll
        for (int r = 0; r < 5; r++) {
            int e = tid + (r << 8);
            int row = e >> 3, j = e & 7;
            cp16(base + SG_BS + (uint32_t)(row * PITCH + j * 8) * 2,
                 Bsrc + (size_t)row * BATCH + kb + j * 8);
        }
        cp_commit();
    };

    float acc[10][4];
    #pragma unroll
    for (int nt = 0; nt < 10; nt++)
        #pragma unroll
        for (int r = 0; r < 4; r++) acc[nt][r] = 0.f;

    int a_row_l = ((lane >> 3) & 1) * 8 + (lane & 7);
    int a_k_l   = (lane >> 4) * 8;
    int b_dn_l  = ((lane >> 4) & 1) * 8 + (lane & 7);
    int b_dk_l  = ((lane >> 3) & 1) * 8;

    issue(0);
    for (int g = 0; g < 12; g++) {
        if (g + 1 < 12) {
            issue(g + 1);
            cp_wait<1>();
        } else {
            cp_wait<0>();
        }
        __syncthreads();
        uint32_t base = sb + (g & 1) * SG_STAGE;
        #pragma unroll
        for (int ks = 0; ks < 4; ks++) {
            uint32_t af[4], bf[10][2];
            int row = warp_m * 16 + a_row_l;
            ldsm4(af[0], af[1], af[2], af[3],
                  base + SG_AS + (uint32_t)(row * PITCH + ks * 16 + a_k_l) * 2);
            #pragma unroll
            for (int p = 0; p < 5; p++) {
                int brow = warp_n * 80 + p * 16 + b_dn_l;
                ldsm4(bf[2*p][0], bf[2*p][1], bf[2*p+1][0], bf[2*p+1][1],
                      base + SG_BS + (uint32_t)(brow * PITCH + ks * 16 + b_dk_l) * 2);
            }
            #pragma unroll
            for (int nt = 0; nt < 10; nt++)
                mma16816(acc[nt], af, bf[nt]);
        }
        __syncthreads();
    }

    // Stage M tile [64][160] fp32 in smem (reuses pipeline buffers).
    float* M_s = (float*)sm;
    int r_l = lane >> 2, c_l = (lane & 3) * 2;
    int row = warp_m * 16 + r_l;
    #pragma unroll
    for (int nt = 0; nt < 10; nt++) {
        int col = warp_n * 80 + nt * 8 + c_l;
        *(float2*)(M_s + row * NDIM + col) = make_float2(acc[nt][0], acc[nt][1]);
        *(float2*)(M_s + (row + 8) * NDIM + col) = make_float2(acc[nt][2], acc[nt][3]);
    }
    __syncthreads();

    // Fused b-update: delta[i,o] = (1/B) sum_{k,u} W[i,o,u,k]*M[i8+k][o16+u]
    #pragma unroll
    for (int ee = 0; ee < 10; ee++) {
        int e = wid * 10 + ee;
        int i_rel = e / 10, o = e - i_rel * 10;
        int i = blockIdx.x * 8 + i_rel;
        float sum = 0.f;
        #pragma unroll
        for (int j = 0; j < 4; j++) {
            int f = lane + (j << 5);           // 0..127
            int k = f >> 4, u = f & 15;
            sum = fmaf(W[(size_t)i * 1280 + (o << 7) + (u << 3) + k],
                       M_s[(i_rel * 8 + k) * NDIM + o * 16 + u], sum);
        }
        #pragma unroll
        for (int off = 16; off; off >>= 1)
            sum += __shfl_xor_sync(0xffffffffu, sum, off);
        if (lane == 0) {
            float d = sum * (1.0f / (float)BATCH);
            int gw = i * OUTCH + o;
            g_b[gw] = (t == 0) ? d : (g_b[gw] + d);
        }
    }
}

// ---------------------------------------------------------------------------
extern "C" void kernel_launch(void* const* d_in, const int* in_sizes, int n_in,
                              void* d_out, int out_size) {
    const float* inp = (const float*)d_in[0];  // [256,1152,8]
    const float* W   = (const float*)d_in[1];  // [1152,10,16,8]
    float* out = (float*)d_out;                // [256,10,16]

    cudaFuncSetAttribute(gemm_s, cudaFuncAttributeMaxDynamicSharedMemorySize, SG2_TOT);
    cudaFuncSetAttribute(gemm_m, cudaFuncAttributeMaxDynamicSharedMemorySize, SG_TOT);

    conv_inp<<<dim3(KDIM / 32, BATCH / 32), dim3(32, 8)>>>(inp);

    for (int t = 0; t < 3; t++) {
        wc_tiled<<<NCHUNK, 256>>>(W, t);
        gemm_s<<<dim3(4, SPLITS_S), 256, SG2_TOT>>>(0);
        squash_k<<<BATCH * NDIM / 64, 256>>>(out, t);
        if (t < 2)
            gemm_m<<<KDIM / 64, 256, SG_TOT>>>(W, t);
    }
}